// round 14
// baseline (speedup 1.0000x reference)
#include <cuda_runtime.h>
#include <cuda_fp16.h>
#include <math.h>
#include <stdint.h>

// Problem constants (B=2, S=2048, H=1024, E=8, I=4096, K=2)
#define Tn 4096
#define Hd 1024
#define Id 4096
#define Ed 8

// ---------------- device scratch ----------------
__device__ int    g_count[Ed];
__device__ int    g_count2[Ed];
__device__ int    g_offset[Ed];
__device__ int    g_top_e[Tn * 2];
__device__ float  g_top_w[Tn * 2];
__device__ int    g_row_tok[Tn * 2];
__device__ int    g_tok_row[Tn * 2];
// 16B+ alignment REQUIRED: cp.async 16B / __half2 accesses trap on misalignment
__device__ __align__(256) __half g_xh[(size_t)Tn * Hd];            // 8 MB
__device__ __align__(256) __half g_wgh[(size_t)Ed * Id * Hd];      // 64 MB
__device__ __align__(256) __half g_wuh[(size_t)Ed * Id * Hd];      // 64 MB
__device__ __align__(256) __half g_wdh[(size_t)Ed * Hd * Id];      // 64 MB
__device__ __align__(256) __half g_hidden_h[(size_t)Tn * 2 * Id];  // 67 MB
__device__ __align__(256) float  g_down[(size_t)Tn * 2 * Hd];      // 33.5 MB

// ---------------- helpers ----------------
__device__ __forceinline__ uint32_t smem_u32(const void* p) {
    uint32_t a;
    asm("{ .reg .u64 t; cvta.to.shared.u64 t, %1; cvt.u32.u64 %0, t; }" : "=r"(a) : "l"(p));
    return a;
}
#define MMA_F16(c, a, b0, b1) \
    asm volatile("mma.sync.aligned.m16n8k16.row.col.f32.f16.f16.f32 " \
                 "{%0,%1,%2,%3}, {%4,%5,%6,%7}, {%8,%9}, {%0,%1,%2,%3};" \
                 : "+f"((c)[0]), "+f"((c)[1]), "+f"((c)[2]), "+f"((c)[3]) \
                 : "r"((a)[0]), "r"((a)[1]), "r"((a)[2]), "r"((a)[3]), \
                   "r"(b0), "r"(b1))
#define CP16(dst_u32, src_ptr) \
    asm volatile("cp.async.cg.shared.global [%0], [%1], 16;" :: "r"(dst_u32), "l"(src_ptr))
__device__ __forceinline__ void cp_commit() { asm volatile("cp.async.commit_group;" ::: "memory"); }
__device__ __forceinline__ void cp_wait1()  { asm volatile("cp.async.wait_group 1;" ::: "memory"); }
__device__ __forceinline__ void cp_wait0()  { asm volatile("cp.async.wait_group 0;" ::: "memory"); }

// ---------------- prep: all fp32->fp16 converts + counter init, ONE launch ----------------
#define XB 2048
#define WB 16384
__device__ __forceinline__ void cvt8(const float* __restrict__ src,
                                     __half* __restrict__ dst, size_t i8) {
    size_t base = i8 * 8;
    float4 a = *(const float4*)(src + base);
    float4 b = *(const float4*)(src + base + 4);
    __half2* d = (__half2*)(dst + base);
    d[0] = __floats2half2_rn(a.x, a.y);
    d[1] = __floats2half2_rn(a.z, a.w);
    d[2] = __floats2half2_rn(b.x, b.y);
    d[3] = __floats2half2_rn(b.z, b.w);
}
__global__ void __launch_bounds__(256) k_prep(const float* __restrict__ x,
                                              const float* __restrict__ wg,
                                              const float* __restrict__ wu,
                                              const float* __restrict__ wd) {
    int b = blockIdx.x;
    if (b == 0 && threadIdx.x < Ed) { g_count[threadIdx.x] = 0; g_count2[threadIdx.x] = 0; }
    if (b < XB) {
        cvt8(x, g_xh, (size_t)b * 256 + threadIdx.x);
    } else if (b < XB + WB) {
        cvt8(wg, g_wgh, (size_t)(b - XB) * 256 + threadIdx.x);
    } else if (b < XB + 2 * WB) {
        cvt8(wu, g_wuh, (size_t)(b - XB - WB) * 256 + threadIdx.x);
    } else {
        cvt8(wd, g_wdh, (size_t)(b - XB - 2 * WB) * 256 + threadIdx.x);
    }
}

// ---------------- router ----------------
__global__ void __launch_bounds__(256) k_router(const float* __restrict__ x,
                                                const float* __restrict__ gw) {
    __shared__ float sgw[Ed * Hd];
    int tid = threadIdx.x;
    for (int i = tid; i < Ed * Hd; i += 256) sgw[i] = gw[i];
    __syncthreads();
    int warp = tid >> 5, lane = tid & 31;
    int t = blockIdx.x * 8 + warp;
    float acc[Ed];
#pragma unroll
    for (int e = 0; e < Ed; e++) acc[e] = 0.f;
    const float* xr = x + (size_t)t * Hd;
    for (int h = lane; h < Hd; h += 32) {
        float xv = xr[h];
#pragma unroll
        for (int e = 0; e < Ed; e++) acc[e] += xv * sgw[e * Hd + h];
    }
#pragma unroll
    for (int e = 0; e < Ed; e++) {
#pragma unroll
        for (int o = 16; o > 0; o >>= 1) acc[e] += __shfl_xor_sync(0xffffffffu, acc[e], o);
    }
    if (lane == 0) {
        float v0 = -1e30f; int e0 = 0;
#pragma unroll
        for (int e = 0; e < Ed; e++) if (acc[e] > v0) { v0 = acc[e]; e0 = e; }
        float v1 = -1e30f; int e1 = 0;
#pragma unroll
        for (int e = 0; e < Ed; e++) if (e != e0 && acc[e] > v1) { v1 = acc[e]; e1 = e; }
        float r  = expf(v1 - v0);
        float w0 = 1.f / (1.f + r);
        float w1 = r / (1.f + r);
        g_top_e[t * 2] = e0;  g_top_e[t * 2 + 1] = e1;
        g_top_w[t * 2] = w0;  g_top_w[t * 2 + 1] = w1;
        atomicAdd(&g_count[e0], 1);
        atomicAdd(&g_count[e1], 1);
    }
}

// ---------------- assign (scan folded in) ----------------
__global__ void __launch_bounds__(256) k_assign() {
    __shared__ int soff[Ed];
    if (threadIdx.x == 0) {
        int o = 0;
#pragma unroll
        for (int e = 0; e < Ed; e++) { soff[e] = o; o += g_count[e]; }
        if (blockIdx.x == 0) {
#pragma unroll
            for (int e = 0; e < Ed; e++) g_offset[e] = soff[e];
        }
    }
    __syncthreads();
    int t = blockIdx.x * 256 + threadIdx.x;
    if (t >= Tn) return;
#pragma unroll
    for (int k = 0; k < 2; k++) {
        int e   = g_top_e[t * 2 + k];
        int pos = atomicAdd(&g_count2[e], 1);
        int row = soff[e] + pos;
        g_row_tok[row]       = t;
        g_tok_row[t * 2 + k] = row;
    }
}

// ================= GEMM1 (fp16 MMA): hidden = silu(x@wg^T) * (x@wu^T) =================
// CTA 192m x 128n, K-chunk 64. 384 threads = 12 warps (3m x 4n); warp 64m x 32n DUAL.
// 3-stage cp.async, ONE barrier per chunk. Rows padded to 72 halves (144 B = 36 words).
#define ROWB 144
#define G1_AB (192 * ROWB)                    // 27648 B
#define G1_BB (128 * ROWB)                    // 18432 B
#define G1_BUFB (G1_AB + 2 * G1_BB)           // 64512 B
#define G1_SMEM (1024 + 3 * G1_BUFB)          // 194560 B
__global__ void __launch_bounds__(384, 1) k_gemm1() {
    int e   = blockIdx.z;
    int cnt = g_count[e];
    int m0  = blockIdx.x * 192;
    if (m0 >= cnt) return;
    int off = g_offset[e];
    int n0  = blockIdx.y * 128;

    extern __shared__ char smc[];
    int* toks = (int*)smc;
    char* bufs = smc + 1024;

    int tid = threadIdx.x;
    int lane = tid & 31, wid = tid >> 5;
    int warp_m = wid >> 2, warp_n = wid & 3;   // 3 x 4
    int g = lane >> 2, tig = lane & 3;

    for (int i = tid; i < 192; i += 384) {
        int m = m0 + i; if (m >= cnt) m = cnt - 1;
        toks[i] = g_row_tok[off + m];
    }
    __syncthreads();

    const __half* wgE = g_wgh + (size_t)e * Id * Hd;
    const __half* wuE = g_wuh + (size_t)e * Id * Hd;
    uint32_t smb = smem_u32(bufs);

    auto prefetch = [&](int c) {
        int k0 = c * 64;
        uint32_t dstb = smb + (c % 3) * G1_BUFB;
#pragma unroll
        for (int p = 0; p < 4; p++) {           // A: 192 rows x 8 quads = 1536 slots
            int idx = tid + 384 * p;
            int r = idx >> 3, q = idx & 7;
            CP16(dstb + r * ROWB + q * 16, g_xh + (size_t)toks[r] * Hd + k0 + q * 8);
        }
#pragma unroll
        for (int p = 0; p < 3; p++) {           // Bg/Bu: 128 x 8 = 1024 slots each
            int idx = tid + 384 * p;
            if (idx < 1024) {
                int r = idx >> 3, q = idx & 7;
                CP16(dstb + G1_AB + r * ROWB + q * 16,
                     wgE + (size_t)(n0 + r) * Hd + k0 + q * 8);
                CP16(dstb + G1_AB + G1_BB + r * ROWB + q * 16,
                     wuE + (size_t)(n0 + r) * Hd + k0 + q * 8);
            }
        }
    };

    float cg[4][4][4] = {}, cu[4][4][4] = {};

    prefetch(0); cp_commit();
    prefetch(1); cp_commit();

    const int NCH = Hd / 64;  // 16
    for (int ch = 0; ch < NCH; ch++) {
        if (ch < NCH - 1) cp_wait1(); else cp_wait0();
        __syncthreads();
        if (ch + 2 < NCH) { prefetch(ch + 2); cp_commit(); }

        const uint32_t* A  = (const uint32_t*)(bufs + (ch % 3) * G1_BUFB);      // 36 w/row
        const uint32_t* Bg = A + G1_AB / 4;
        const uint32_t* Bu = Bg + G1_BB / 4;
#pragma unroll
        for (int kk = 0; kk < 4; kk++) {
            int w0 = kk * 8;
            uint32_t a[4][4];
#pragma unroll
            for (int i = 0; i < 4; i++) {
                int r = warp_m * 64 + i * 16 + g;
                a[i][0] = A[r * 36 + w0 + tig];
                a[i][1] = A[(r + 8) * 36 + w0 + tig];
                a[i][2] = A[r * 36 + w0 + tig + 4];
                a[i][3] = A[(r + 8) * 36 + w0 + tig + 4];
            }
#pragma unroll
            for (int j = 0; j < 4; j++) {
                int n = warp_n * 32 + j * 8 + g;
                uint32_t bg0 = Bg[n * 36 + w0 + tig], bg1 = Bg[n * 36 + w0 + tig + 4];
                uint32_t bu0 = Bu[n * 36 + w0 + tig], bu1 = Bu[n * 36 + w0 + tig + 4];
#pragma unroll
                for (int i = 0; i < 4; i++) {
                    MMA_F16(cg[i][j], a[i], bg0, bg1);
                    MMA_F16(cu[i][j], a[i], bu0, bu1);
                }
            }
        }
    }

    // epilogue: silu(gate)*up -> g_hidden_h
#pragma unroll
    for (int i = 0; i < 4; i++) {
        int rb = m0 + warp_m * 64 + i * 16 + g;
#pragma unroll
        for (int j = 0; j < 4; j++) {
            int n = n0 + warp_n * 32 + j * 8 + 2 * tig;
            if (rb < cnt) {
                size_t base = (size_t)(off + rb) * Id + n;
                float g0 = cg[i][j][0], g1 = cg[i][j][1];
                float h0 = g0 / (1.f + expf(-g0)) * cu[i][j][0];
                float h1 = g1 / (1.f + expf(-g1)) * cu[i][j][1];
                *(__half2*)(g_hidden_h + base) = __floats2half2_rn(h0, h1);
            }
            if (rb + 8 < cnt) {
                size_t base = (size_t)(off + rb + 8) * Id + n;
                float g2 = cg[i][j][2], g3 = cg[i][j][3];
                float h2 = g2 / (1.f + expf(-g2)) * cu[i][j][2];
                float h3 = g3 / (1.f + expf(-g3)) * cu[i][j][3];
                *(__half2*)(g_hidden_h + base) = __floats2half2_rn(h2, h3);
            }
        }
    }
}

// ================= GEMM2 (fp16 MMA): down = hidden @ wd^T =================
// CTA 384m x 128n, K-chunk 64. 384 threads = 12 warps (6m x 2n); warp 64m x 64n.
// 3-stage cp.async, ONE barrier per chunk.
#define G2_AB (384 * ROWB)                    // 55296 B
#define G2_BB (128 * ROWB)                    // 18432 B
#define G2_BUFB (G2_AB + G2_BB)               // 73728 B
#define G2_SMEM (3 * G2_BUFB)                 // 221184 B
__global__ void __launch_bounds__(384, 1) k_gemm2() {
    int e   = blockIdx.z;
    int cnt = g_count[e];
    int m0  = blockIdx.x * 384;
    if (m0 >= cnt) return;
    int off = g_offset[e];
    int n0  = blockIdx.y * 128;

    extern __shared__ char smc[];
    char* bufs = smc;

    int tid = threadIdx.x;
    int lane = tid & 31, wid = tid >> 5;
    int warp_m = wid >> 1, warp_n = wid & 1;   // 6 x 2
    int g = lane >> 2, tig = lane & 3;

    const __half* wdE = g_wdh + (size_t)e * Hd * Id;
    uint32_t smb = smem_u32(bufs);

    auto prefetch = [&](int c) {
        int k0 = c * 64;
        uint32_t dstb = smb + (c % 3) * G2_BUFB;
#pragma unroll
        for (int p = 0; p < 8; p++) {           // A: 384 x 8 = 3072 slots
            int idx = tid + 384 * p;
            int r = idx >> 3, q = idx & 7;
            int am = m0 + r; if (am >= cnt) am = cnt - 1;
            CP16(dstb + r * ROWB + q * 16,
                 g_hidden_h + (size_t)(off + am) * Id + k0 + q * 8);
        }
#pragma unroll
        for (int p = 0; p < 3; p++) {           // B: 128 x 8 = 1024 slots
            int idx = tid + 384 * p;
            if (idx < 1024) {
                int r = idx >> 3, q = idx & 7;
                CP16(dstb + G2_AB + r * ROWB + q * 16,
                     wdE + (size_t)(n0 + r) * Id + k0 + q * 8);
            }
        }
    };

    float c[4][8][4] = {};

    prefetch(0); cp_commit();
    prefetch(1); cp_commit();

    const int NCH = Id / 64;  // 64
    for (int ch = 0; ch < NCH; ch++) {
        if (ch < NCH - 1) cp_wait1(); else cp_wait0();
        __syncthreads();
        if (ch + 2 < NCH) { prefetch(ch + 2); cp_commit(); }

        const uint32_t* A = (const uint32_t*)(bufs + (ch % 3) * G2_BUFB);
        const uint32_t* B = A + G2_AB / 4;
#pragma unroll
        for (int kk = 0; kk < 4; kk++) {
            int w0 = kk * 8;
            uint32_t a[4][4];
#pragma unroll
            for (int i = 0; i < 4; i++) {
                int r = warp_m * 64 + i * 16 + g;
                a[i][0] = A[r * 36 + w0 + tig];
                a[i][1] = A[(r + 8) * 36 + w0 + tig];
                a[i][2] = A[r * 36 + w0 + tig + 4];
                a[i][3] = A[(r + 8) * 36 + w0 + tig + 4];
            }
#pragma unroll
            for (int j = 0; j < 8; j++) {
                int n = warp_n * 64 + j * 8 + g;
                uint32_t b0 = B[n * 36 + w0 + tig], b1 = B[n * 36 + w0 + tig + 4];
#pragma unroll
                for (int i = 0; i < 4; i++) MMA_F16(c[i][j], a[i], b0, b1);
            }
        }
    }

#pragma unroll
    for (int i = 0; i < 4; i++) {
        int rb = m0 + warp_m * 64 + i * 16 + g;
#pragma unroll
        for (int j = 0; j < 8; j++) {
            int n = n0 + warp_n * 64 + j * 8 + 2 * tig;
            if (rb < cnt) {
                size_t base = (size_t)(off + rb) * Hd + n;
                g_down[base]     = c[i][j][0];
                g_down[base + 1] = c[i][j][1];
            }
            if (rb + 8 < cnt) {
                size_t base = (size_t)(off + rb + 8) * Hd + n;
                g_down[base]     = c[i][j][2];
                g_down[base + 1] = c[i][j][3];
            }
        }
    }
}

// ---------------- combine ----------------
__global__ void __launch_bounds__(256) k_combine(float* __restrict__ out) {
    int idx = blockIdx.x * 256 + threadIdx.x;
    int t   = idx >> 8;
    int c4  = (idx & 255) << 2;
    int r0  = g_tok_row[t * 2];
    int r1  = g_tok_row[t * 2 + 1];
    float w0 = g_top_w[t * 2];
    float w1 = g_top_w[t * 2 + 1];
    float4 d0 = *(const float4*)(g_down + (size_t)r0 * Hd + c4);
    float4 d1 = *(const float4*)(g_down + (size_t)r1 * Hd + c4);
    float4 o;
    o.x = w0 * d0.x + w1 * d1.x;
    o.y = w0 * d0.y + w1 * d1.y;
    o.z = w0 * d0.z + w1 * d1.z;
    o.w = w0 * d0.w + w1 * d1.w;
    *(float4*)(out + (size_t)t * Hd + c4) = o;
}

// ---------------- launch ----------------
extern "C" void kernel_launch(void* const* d_in, const int* in_sizes, int n_in,
                              void* d_out, int out_size) {
    const float* x  = (const float*)d_in[0];
    const float* gw = (const float*)d_in[1];
    const float* wg = (const float*)d_in[2];
    const float* wu = (const float*)d_in[3];
    const float* wd = (const float*)d_in[4];
    float* out = (float*)d_out;

    cudaFuncSetAttribute(k_gemm1, cudaFuncAttributeMaxDynamicSharedMemorySize, G1_SMEM);
    cudaFuncSetAttribute(k_gemm2, cudaFuncAttributeMaxDynamicSharedMemorySize, G2_SMEM);

    // launch 0: converts + init
    k_prep<<<XB + 3 * WB, 256>>>(x, wg, wu, wd);
    // launch 1: router
    k_router<<<Tn / 8, 256>>>(x, gw);
    // launch 2: assign
    k_assign<<<Tn / 256, 256>>>();

    // launch 3: GEMM1 (ncu profiles launch index 3)
    dim3 g1(22, 32, Ed);   // ceil(4096/192) x (4096/128) x experts
    k_gemm1<<<g1, 384, G1_SMEM>>>();

    // launch 4: GEMM2
    dim3 g2(11, 8, Ed);    // ceil(4096/384) x (1024/128) x experts
    k_gemm2<<<g2, 384, G2_SMEM>>>();

    // launch 5: combine
    k_combine<<<Tn * Hd / 1024, 256>>>(out);
}

// round 15
// speedup vs baseline: 1.1288x; 1.1288x over previous
#include <cuda_runtime.h>
#include <cuda_fp16.h>
#include <math.h>
#include <stdint.h>

// Problem constants (B=2, S=2048, H=1024, E=8, I=4096, K=2)
#define Tn 4096
#define Hd 1024
#define Id 4096
#define Ed 8

// ---------------- device scratch ----------------
__device__ int    g_count[Ed];
__device__ int    g_count2[Ed];
__device__ int    g_offset[Ed];
__device__ int    g_top_e[Tn * 2];
__device__ float  g_top_w[Tn * 2];
__device__ int    g_row_tok[Tn * 2];
__device__ int    g_tok_row[Tn * 2];
// 16B+ alignment REQUIRED: cp.async 16B / __half2 accesses trap on misalignment
__device__ __align__(256) __half g_xh[(size_t)Tn * Hd];            // 8 MB
__device__ __align__(256) __half g_wgh[(size_t)Ed * Id * Hd];      // 64 MB
__device__ __align__(256) __half g_wuh[(size_t)Ed * Id * Hd];      // 64 MB
__device__ __align__(256) __half g_wdh[(size_t)Ed * Hd * Id];      // 64 MB
__device__ __align__(256) __half g_hidden_h[(size_t)Tn * 2 * Id];  // 67 MB
__device__ __align__(256) float  g_down[(size_t)Tn * 2 * Hd];      // 33.5 MB

// ---------------- helpers ----------------
__device__ __forceinline__ uint32_t smem_u32(const void* p) {
    uint32_t a;
    asm("{ .reg .u64 t; cvta.to.shared.u64 t, %1; cvt.u32.u64 %0, t; }" : "=r"(a) : "l"(p));
    return a;
}
#define MMA_F16(c, a, b0, b1) \
    asm volatile("mma.sync.aligned.m16n8k16.row.col.f32.f16.f16.f32 " \
                 "{%0,%1,%2,%3}, {%4,%5,%6,%7}, {%8,%9}, {%0,%1,%2,%3};" \
                 : "+f"((c)[0]), "+f"((c)[1]), "+f"((c)[2]), "+f"((c)[3]) \
                 : "r"((a)[0]), "r"((a)[1]), "r"((a)[2]), "r"((a)[3]), \
                   "r"(b0), "r"(b1))
#define LDSM4(r0, r1, r2, r3, addr) \
    asm volatile("ldmatrix.sync.aligned.m8n8.x4.shared.b16 {%0,%1,%2,%3}, [%4];" \
                 : "=r"(r0), "=r"(r1), "=r"(r2), "=r"(r3) : "r"(addr))
#define LDSM2(r0, r1, addr) \
    asm volatile("ldmatrix.sync.aligned.m8n8.x2.shared.b16 {%0,%1}, [%2];" \
                 : "=r"(r0), "=r"(r1) : "r"(addr))
#define CP16(dst_u32, src_ptr) \
    asm volatile("cp.async.cg.shared.global [%0], [%1], 16;" :: "r"(dst_u32), "l"(src_ptr))
__device__ __forceinline__ void cp_commit() { asm volatile("cp.async.commit_group;" ::: "memory"); }
__device__ __forceinline__ void cp_wait1()  { asm volatile("cp.async.wait_group 1;" ::: "memory"); }
__device__ __forceinline__ void cp_wait0()  { asm volatile("cp.async.wait_group 0;" ::: "memory"); }

// ---------------- prep: all fp32->fp16 converts + counter init, ONE launch ----------------
#define XB 2048
#define WB 16384
__device__ __forceinline__ void cvt8(const float* __restrict__ src,
                                     __half* __restrict__ dst, size_t i8) {
    size_t base = i8 * 8;
    float4 a = *(const float4*)(src + base);
    float4 b = *(const float4*)(src + base + 4);
    __half2* d = (__half2*)(dst + base);
    d[0] = __floats2half2_rn(a.x, a.y);
    d[1] = __floats2half2_rn(a.z, a.w);
    d[2] = __floats2half2_rn(b.x, b.y);
    d[3] = __floats2half2_rn(b.z, b.w);
}
__global__ void __launch_bounds__(256) k_prep(const float* __restrict__ x,
                                              const float* __restrict__ wg,
                                              const float* __restrict__ wu,
                                              const float* __restrict__ wd) {
    int b = blockIdx.x;
    if (b == 0 && threadIdx.x < Ed) { g_count[threadIdx.x] = 0; g_count2[threadIdx.x] = 0; }
    if (b < XB) {
        cvt8(x, g_xh, (size_t)b * 256 + threadIdx.x);
    } else if (b < XB + WB) {
        cvt8(wg, g_wgh, (size_t)(b - XB) * 256 + threadIdx.x);
    } else if (b < XB + 2 * WB) {
        cvt8(wu, g_wuh, (size_t)(b - XB - WB) * 256 + threadIdx.x);
    } else {
        cvt8(wd, g_wdh, (size_t)(b - XB - 2 * WB) * 256 + threadIdx.x);
    }
}

// ---------------- router ----------------
__global__ void __launch_bounds__(256) k_router(const float* __restrict__ x,
                                                const float* __restrict__ gw) {
    __shared__ float sgw[Ed * Hd];
    int tid = threadIdx.x;
    for (int i = tid; i < Ed * Hd; i += 256) sgw[i] = gw[i];
    __syncthreads();
    int warp = tid >> 5, lane = tid & 31;
    int t = blockIdx.x * 8 + warp;
    float acc[Ed];
#pragma unroll
    for (int e = 0; e < Ed; e++) acc[e] = 0.f;
    const float* xr = x + (size_t)t * Hd;
    for (int h = lane; h < Hd; h += 32) {
        float xv = xr[h];
#pragma unroll
        for (int e = 0; e < Ed; e++) acc[e] += xv * sgw[e * Hd + h];
    }
#pragma unroll
    for (int e = 0; e < Ed; e++) {
#pragma unroll
        for (int o = 16; o > 0; o >>= 1) acc[e] += __shfl_xor_sync(0xffffffffu, acc[e], o);
    }
    if (lane == 0) {
        float v0 = -1e30f; int e0 = 0;
#pragma unroll
        for (int e = 0; e < Ed; e++) if (acc[e] > v0) { v0 = acc[e]; e0 = e; }
        float v1 = -1e30f; int e1 = 0;
#pragma unroll
        for (int e = 0; e < Ed; e++) if (e != e0 && acc[e] > v1) { v1 = acc[e]; e1 = e; }
        float r  = expf(v1 - v0);
        float w0 = 1.f / (1.f + r);
        float w1 = r / (1.f + r);
        g_top_e[t * 2] = e0;  g_top_e[t * 2 + 1] = e1;
        g_top_w[t * 2] = w0;  g_top_w[t * 2 + 1] = w1;
        atomicAdd(&g_count[e0], 1);
        atomicAdd(&g_count[e1], 1);
    }
}

// ---------------- assign (scan folded in) ----------------
__global__ void __launch_bounds__(256) k_assign() {
    __shared__ int soff[Ed];
    if (threadIdx.x == 0) {
        int o = 0;
#pragma unroll
        for (int e = 0; e < Ed; e++) { soff[e] = o; o += g_count[e]; }
        if (blockIdx.x == 0) {
#pragma unroll
            for (int e = 0; e < Ed; e++) g_offset[e] = soff[e];
        }
    }
    __syncthreads();
    int t = blockIdx.x * 256 + threadIdx.x;
    if (t >= Tn) return;
#pragma unroll
    for (int k = 0; k < 2; k++) {
        int e   = g_top_e[t * 2 + k];
        int pos = atomicAdd(&g_count2[e], 1);
        int row = soff[e] + pos;
        g_row_tok[row]       = t;
        g_tok_row[t * 2 + k] = row;
    }
}

// ================= GEMM1 (fp16 MMA + ldmatrix): hidden = silu(x@wg^T)*(x@wu^T) ========
// CTA 192m x 128n, K-chunk 64. 384 threads = 12 warps (3m x 4n); warp 64m x 32n DUAL.
// 3-stage cp.async, ONE barrier per chunk. Rows padded to 72 halves (144 B).
#define ROWB 144
#define G1_AB (192 * ROWB)                    // 27648 B
#define G1_BB (128 * ROWB)                    // 18432 B
#define G1_BUFB (G1_AB + 2 * G1_BB)           // 64512 B
#define G1_SMEM (1024 + 3 * G1_BUFB)          // 194560 B
__global__ void __launch_bounds__(384, 1) k_gemm1() {
    int e   = blockIdx.z;
    int cnt = g_count[e];
    int m0  = blockIdx.x * 192;
    if (m0 >= cnt) return;
    int off = g_offset[e];
    int n0  = blockIdx.y * 128;

    extern __shared__ char smc[];
    int* toks = (int*)smc;
    char* bufs = smc + 1024;

    int tid = threadIdx.x;
    int lane = tid & 31, wid = tid >> 5;
    int warp_m = wid >> 2, warp_n = wid & 3;   // 3 x 4
    int g = lane >> 2, tig = lane & 3;

    for (int i = tid; i < 192; i += 384) {
        int m = m0 + i; if (m >= cnt) m = cnt - 1;
        toks[i] = g_row_tok[off + m];
    }
    __syncthreads();

    const __half* wgE = g_wgh + (size_t)e * Id * Hd;
    const __half* wuE = g_wuh + (size_t)e * Id * Hd;
    uint32_t smb = smem_u32(bufs);

    // per-lane ldmatrix base offsets (within buffer)
    uint32_t a_lo[4], b_lo[4];
#pragma unroll
    for (int i = 0; i < 4; i++) {
        int r = warp_m * 64 + i * 16 + (lane & 15);
        a_lo[i] = r * ROWB + (lane >> 4) * 16;
    }
#pragma unroll
    for (int j = 0; j < 4; j++) {
        int n = warp_n * 32 + j * 8 + (lane & 7);
        b_lo[j] = n * ROWB + ((lane >> 3) & 1) * 16;
    }

    auto prefetch = [&](int c) {
        int k0 = c * 64;
        uint32_t dstb = smb + (c % 3) * G1_BUFB;
#pragma unroll
        for (int p = 0; p < 4; p++) {           // A: 192 rows x 8 quads = 1536 slots
            int idx = tid + 384 * p;
            int r = idx >> 3, q = idx & 7;
            CP16(dstb + r * ROWB + q * 16, g_xh + (size_t)toks[r] * Hd + k0 + q * 8);
        }
#pragma unroll
        for (int p = 0; p < 3; p++) {           // Bg/Bu: 128 x 8 = 1024 slots each
            int idx = tid + 384 * p;
            if (idx < 1024) {
                int r = idx >> 3, q = idx & 7;
                CP16(dstb + G1_AB + r * ROWB + q * 16,
                     wgE + (size_t)(n0 + r) * Hd + k0 + q * 8);
                CP16(dstb + G1_AB + G1_BB + r * ROWB + q * 16,
                     wuE + (size_t)(n0 + r) * Hd + k0 + q * 8);
            }
        }
    };

    float cg[4][4][4] = {}, cu[4][4][4] = {};

    prefetch(0); cp_commit();
    prefetch(1); cp_commit();

    const int NCH = Hd / 64;  // 16
    for (int ch = 0; ch < NCH; ch++) {
        if (ch < NCH - 1) cp_wait1(); else cp_wait0();
        __syncthreads();
        if (ch + 2 < NCH) { prefetch(ch + 2); cp_commit(); }

        uint32_t bb = smb + (ch % 3) * G1_BUFB;
#pragma unroll
        for (int kk = 0; kk < 4; kk++) {
            uint32_t ko = kk * 32;             // 16 halves = 32 B per kk
            uint32_t a[4][4];
#pragma unroll
            for (int i = 0; i < 4; i++)
                LDSM4(a[i][0], a[i][1], a[i][2], a[i][3], bb + a_lo[i] + ko);
#pragma unroll
            for (int j = 0; j < 4; j++) {
                uint32_t bg0, bg1, bu0, bu1;
                LDSM2(bg0, bg1, bb + G1_AB + b_lo[j] + ko);
                LDSM2(bu0, bu1, bb + G1_AB + G1_BB + b_lo[j] + ko);
#pragma unroll
                for (int i = 0; i < 4; i++) {
                    MMA_F16(cg[i][j], a[i], bg0, bg1);
                    MMA_F16(cu[i][j], a[i], bu0, bu1);
                }
            }
        }
    }

    // epilogue: silu(gate)*up -> g_hidden_h
#pragma unroll
    for (int i = 0; i < 4; i++) {
        int rb = m0 + warp_m * 64 + i * 16 + g;
#pragma unroll
        for (int j = 0; j < 4; j++) {
            int n = n0 + warp_n * 32 + j * 8 + 2 * tig;
            if (rb < cnt) {
                size_t base = (size_t)(off + rb) * Id + n;
                float g0 = cg[i][j][0], g1 = cg[i][j][1];
                float h0 = g0 / (1.f + expf(-g0)) * cu[i][j][0];
                float h1 = g1 / (1.f + expf(-g1)) * cu[i][j][1];
                *(__half2*)(g_hidden_h + base) = __floats2half2_rn(h0, h1);
            }
            if (rb + 8 < cnt) {
                size_t base = (size_t)(off + rb + 8) * Id + n;
                float g2 = cg[i][j][2], g3 = cg[i][j][3];
                float h2 = g2 / (1.f + expf(-g2)) * cu[i][j][2];
                float h3 = g3 / (1.f + expf(-g3)) * cu[i][j][3];
                *(__half2*)(g_hidden_h + base) = __floats2half2_rn(h2, h3);
            }
        }
    }
}

// ================= GEMM2 (fp16 MMA + ldmatrix): down = hidden @ wd^T =================
// CTA 256m x 128n, K-chunk 64. 512 threads = 16 warps (4m x 4n); warp 64m x 32n.
// 3-stage cp.async, ONE barrier per chunk.
#define G2_AB (256 * ROWB)                    // 36864 B
#define G2_BB (128 * ROWB)                    // 18432 B
#define G2_BUFB (G2_AB + G2_BB)               // 55296 B
#define G2_SMEM (3 * G2_BUFB)                 // 165888 B
__global__ void __launch_bounds__(512, 1) k_gemm2() {
    int e   = blockIdx.z;
    int cnt = g_count[e];
    int m0  = blockIdx.x * 256;
    if (m0 >= cnt) return;
    int off = g_offset[e];
    int n0  = blockIdx.y * 128;

    extern __shared__ char smc[];
    char* bufs = smc;

    int tid = threadIdx.x;
    int lane = tid & 31, wid = tid >> 5;
    int warp_m = wid >> 2, warp_n = wid & 3;   // 4 x 4
    int g = lane >> 2, tig = lane & 3;

    const __half* wdE = g_wdh + (size_t)e * Hd * Id;
    uint32_t smb = smem_u32(bufs);

    uint32_t a_lo[4], b_lo[4];
#pragma unroll
    for (int i = 0; i < 4; i++) {
        int r = warp_m * 64 + i * 16 + (lane & 15);
        a_lo[i] = r * ROWB + (lane >> 4) * 16;
    }
#pragma unroll
    for (int j = 0; j < 4; j++) {
        int n = warp_n * 32 + j * 8 + (lane & 7);
        b_lo[j] = n * ROWB + ((lane >> 3) & 1) * 16;
    }

    auto prefetch = [&](int c) {
        int k0 = c * 64;
        uint32_t dstb = smb + (c % 3) * G2_BUFB;
#pragma unroll
        for (int p = 0; p < 4; p++) {           // A: 256 x 8 = 2048 slots
            int idx = tid + 512 * p;
            int r = idx >> 3, q = idx & 7;
            int am = m0 + r; if (am >= cnt) am = cnt - 1;
            CP16(dstb + r * ROWB + q * 16,
                 g_hidden_h + (size_t)(off + am) * Id + k0 + q * 8);
        }
#pragma unroll
        for (int p = 0; p < 2; p++) {           // B: 128 x 8 = 1024 slots
            int idx = tid + 512 * p;
            int r = idx >> 3, q = idx & 7;
            CP16(dstb + G2_AB + r * ROWB + q * 16,
                 wdE + (size_t)(n0 + r) * Id + k0 + q * 8);
        }
    };

    float c[4][4][4] = {};

    prefetch(0); cp_commit();
    prefetch(1); cp_commit();

    const int NCH = Id / 64;  // 64
    for (int ch = 0; ch < NCH; ch++) {
        if (ch < NCH - 1) cp_wait1(); else cp_wait0();
        __syncthreads();
        if (ch + 2 < NCH) { prefetch(ch + 2); cp_commit(); }

        uint32_t bb = smb + (ch % 3) * G2_BUFB;
#pragma unroll
        for (int kk = 0; kk < 4; kk++) {
            uint32_t ko = kk * 32;
            uint32_t a[4][4];
#pragma unroll
            for (int i = 0; i < 4; i++)
                LDSM4(a[i][0], a[i][1], a[i][2], a[i][3], bb + a_lo[i] + ko);
#pragma unroll
            for (int j = 0; j < 4; j++) {
                uint32_t b0, b1;
                LDSM2(b0, b1, bb + G2_AB + b_lo[j] + ko);
#pragma unroll
                for (int i = 0; i < 4; i++) MMA_F16(c[i][j], a[i], b0, b1);
            }
        }
    }

#pragma unroll
    for (int i = 0; i < 4; i++) {
        int rb = m0 + warp_m * 64 + i * 16 + g;
#pragma unroll
        for (int j = 0; j < 4; j++) {
            int n = n0 + warp_n * 32 + j * 8 + 2 * tig;
            if (rb < cnt) {
                size_t base = (size_t)(off + rb) * Hd + n;
                g_down[base]     = c[i][j][0];
                g_down[base + 1] = c[i][j][1];
            }
            if (rb + 8 < cnt) {
                size_t base = (size_t)(off + rb + 8) * Hd + n;
                g_down[base]     = c[i][j][2];
                g_down[base + 1] = c[i][j][3];
            }
        }
    }
}

// ---------------- combine ----------------
__global__ void __launch_bounds__(256) k_combine(float* __restrict__ out) {
    int idx = blockIdx.x * 256 + threadIdx.x;
    int t   = idx >> 8;
    int c4  = (idx & 255) << 2;
    int r0  = g_tok_row[t * 2];
    int r1  = g_tok_row[t * 2 + 1];
    float w0 = g_top_w[t * 2];
    float w1 = g_top_w[t * 2 + 1];
    float4 d0 = *(const float4*)(g_down + (size_t)r0 * Hd + c4);
    float4 d1 = *(const float4*)(g_down + (size_t)r1 * Hd + c4);
    float4 o;
    o.x = w0 * d0.x + w1 * d1.x;
    o.y = w0 * d0.y + w1 * d1.y;
    o.z = w0 * d0.z + w1 * d1.z;
    o.w = w0 * d0.w + w1 * d1.w;
    *(float4*)(out + (size_t)t * Hd + c4) = o;
}

// ---------------- launch ----------------
extern "C" void kernel_launch(void* const* d_in, const int* in_sizes, int n_in,
                              void* d_out, int out_size) {
    const float* x  = (const float*)d_in[0];
    const float* gw = (const float*)d_in[1];
    const float* wg = (const float*)d_in[2];
    const float* wu = (const float*)d_in[3];
    const float* wd = (const float*)d_in[4];
    float* out = (float*)d_out;

    cudaFuncSetAttribute(k_gemm1, cudaFuncAttributeMaxDynamicSharedMemorySize, G1_SMEM);
    cudaFuncSetAttribute(k_gemm2, cudaFuncAttributeMaxDynamicSharedMemorySize, G2_SMEM);

    // launch 0: converts + init
    k_prep<<<XB + 3 * WB, 256>>>(x, wg, wu, wd);
    // launch 1: router
    k_router<<<Tn / 8, 256>>>(x, gw);
    // launch 2: assign
    k_assign<<<Tn / 256, 256>>>();

    // launch 3: GEMM1 (ncu profiles launch index 3)
    dim3 g1(22, 32, Ed);   // ceil(4096/192) x (4096/128) x experts
    k_gemm1<<<g1, 384, G1_SMEM>>>();

    // launch 4: GEMM2
    dim3 g2(16, 8, Ed);    // (4096/256) x (1024/128) x experts
    k_gemm2<<<g2, 512, G2_SMEM>>>();

    // launch 5: combine
    k_combine<<<Tn * Hd / 1024, 256>>>(out);
}

// round 16
// speedup vs baseline: 1.1526x; 1.0211x over previous
#include <cuda_runtime.h>
#include <cuda_fp16.h>
#include <math.h>
#include <stdint.h>

// Problem constants (B=2, S=2048, H=1024, E=8, I=4096, K=2)
#define Tn 4096
#define Hd 1024
#define Id 4096
#define Ed 8

// ---------------- device scratch ----------------
__device__ int    g_count[Ed];
__device__ int    g_count2[Ed];
__device__ int    g_offset[Ed];
__device__ int    g_top_e[Tn * 2];
__device__ float  g_top_w[Tn * 2];
__device__ int    g_row_tok[Tn * 2];
__device__ int    g_tok_row[Tn * 2];
// 16B+ alignment REQUIRED: cp.async 16B / __half2 accesses trap on misalignment
__device__ __align__(256) __half g_xh[(size_t)Tn * Hd];            // 8 MB
__device__ __align__(256) __half g_wgh[(size_t)Ed * Id * Hd];      // 64 MB
__device__ __align__(256) __half g_wuh[(size_t)Ed * Id * Hd];      // 64 MB
__device__ __align__(256) __half g_wdh[(size_t)Ed * Hd * Id];      // 64 MB
__device__ __align__(256) __half g_hidden_h[(size_t)Tn * 2 * Id];  // 67 MB
__device__ __align__(256) float  g_down[(size_t)Tn * 2 * Hd];      // 33.5 MB

// ---------------- helpers ----------------
__device__ __forceinline__ uint32_t smem_u32(const void* p) {
    uint32_t a;
    asm("{ .reg .u64 t; cvta.to.shared.u64 t, %1; cvt.u32.u64 %0, t; }" : "=r"(a) : "l"(p));
    return a;
}
#define MMA_F16(c, a, b0, b1) \
    asm volatile("mma.sync.aligned.m16n8k16.row.col.f32.f16.f16.f32 " \
                 "{%0,%1,%2,%3}, {%4,%5,%6,%7}, {%8,%9}, {%0,%1,%2,%3};" \
                 : "+f"((c)[0]), "+f"((c)[1]), "+f"((c)[2]), "+f"((c)[3]) \
                 : "r"((a)[0]), "r"((a)[1]), "r"((a)[2]), "r"((a)[3]), \
                   "r"(b0), "r"(b1))
#define LDSM4(r0, r1, r2, r3, addr) \
    asm volatile("ldmatrix.sync.aligned.m8n8.x4.shared.b16 {%0,%1,%2,%3}, [%4];" \
                 : "=r"(r0), "=r"(r1), "=r"(r2), "=r"(r3) : "r"(addr))
#define LDSM2(r0, r1, addr) \
    asm volatile("ldmatrix.sync.aligned.m8n8.x2.shared.b16 {%0,%1}, [%2];" \
                 : "=r"(r0), "=r"(r1) : "r"(addr))
#define CP16(dst_u32, src_ptr) \
    asm volatile("cp.async.cg.shared.global [%0], [%1], 16;" :: "r"(dst_u32), "l"(src_ptr))
__device__ __forceinline__ void cp_commit() { asm volatile("cp.async.commit_group;" ::: "memory"); }
__device__ __forceinline__ void cp_wait1()  { asm volatile("cp.async.wait_group 1;" ::: "memory"); }
__device__ __forceinline__ void cp_wait0()  { asm volatile("cp.async.wait_group 0;" ::: "memory"); }

// ---------------- prep: all fp32->fp16 converts + counter init, ONE launch ----------------
#define XB 2048
#define WB 16384
__device__ __forceinline__ void cvt8(const float* __restrict__ src,
                                     __half* __restrict__ dst, size_t i8) {
    size_t base = i8 * 8;
    float4 a = *(const float4*)(src + base);
    float4 b = *(const float4*)(src + base + 4);
    __half2* d = (__half2*)(dst + base);
    d[0] = __floats2half2_rn(a.x, a.y);
    d[1] = __floats2half2_rn(a.z, a.w);
    d[2] = __floats2half2_rn(b.x, b.y);
    d[3] = __floats2half2_rn(b.z, b.w);
}
__global__ void __launch_bounds__(256) k_prep(const float* __restrict__ x,
                                              const float* __restrict__ wg,
                                              const float* __restrict__ wu,
                                              const float* __restrict__ wd) {
    int b = blockIdx.x;
    if (b == 0 && threadIdx.x < Ed) { g_count[threadIdx.x] = 0; g_count2[threadIdx.x] = 0; }
    if (b < XB) {
        cvt8(x, g_xh, (size_t)b * 256 + threadIdx.x);
    } else if (b < XB + WB) {
        cvt8(wg, g_wgh, (size_t)(b - XB) * 256 + threadIdx.x);
    } else if (b < XB + 2 * WB) {
        cvt8(wu, g_wuh, (size_t)(b - XB - WB) * 256 + threadIdx.x);
    } else {
        cvt8(wd, g_wdh, (size_t)(b - XB - 2 * WB) * 256 + threadIdx.x);
    }
}

// ---------------- router ----------------
__global__ void __launch_bounds__(256) k_router(const float* __restrict__ x,
                                                const float* __restrict__ gw) {
    __shared__ float sgw[Ed * Hd];
    int tid = threadIdx.x;
    for (int i = tid; i < Ed * Hd; i += 256) sgw[i] = gw[i];
    __syncthreads();
    int warp = tid >> 5, lane = tid & 31;
    int t = blockIdx.x * 8 + warp;
    float acc[Ed];
#pragma unroll
    for (int e = 0; e < Ed; e++) acc[e] = 0.f;
    const float* xr = x + (size_t)t * Hd;
    for (int h = lane; h < Hd; h += 32) {
        float xv = xr[h];
#pragma unroll
        for (int e = 0; e < Ed; e++) acc[e] += xv * sgw[e * Hd + h];
    }
#pragma unroll
    for (int e = 0; e < Ed; e++) {
#pragma unroll
        for (int o = 16; o > 0; o >>= 1) acc[e] += __shfl_xor_sync(0xffffffffu, acc[e], o);
    }
    if (lane == 0) {
        float v0 = -1e30f; int e0 = 0;
#pragma unroll
        for (int e = 0; e < Ed; e++) if (acc[e] > v0) { v0 = acc[e]; e0 = e; }
        float v1 = -1e30f; int e1 = 0;
#pragma unroll
        for (int e = 0; e < Ed; e++) if (e != e0 && acc[e] > v1) { v1 = acc[e]; e1 = e; }
        float r  = expf(v1 - v0);
        float w0 = 1.f / (1.f + r);
        float w1 = r / (1.f + r);
        g_top_e[t * 2] = e0;  g_top_e[t * 2 + 1] = e1;
        g_top_w[t * 2] = w0;  g_top_w[t * 2 + 1] = w1;
        atomicAdd(&g_count[e0], 1);
        atomicAdd(&g_count[e1], 1);
    }
}

// ---------------- assign (scan folded in) ----------------
__global__ void __launch_bounds__(256) k_assign() {
    __shared__ int soff[Ed];
    if (threadIdx.x == 0) {
        int o = 0;
#pragma unroll
        for (int e = 0; e < Ed; e++) { soff[e] = o; o += g_count[e]; }
        if (blockIdx.x == 0) {
#pragma unroll
            for (int e = 0; e < Ed; e++) g_offset[e] = soff[e];
        }
    }
    __syncthreads();
    int t = blockIdx.x * 256 + threadIdx.x;
    if (t >= Tn) return;
#pragma unroll
    for (int k = 0; k < 2; k++) {
        int e   = g_top_e[t * 2 + k];
        int pos = atomicAdd(&g_count2[e], 1);
        int row = soff[e] + pos;
        g_row_tok[row]       = t;
        g_tok_row[t * 2 + k] = row;
    }
}

// ================= GEMM1 (fp16 MMA + ldmatrix): hidden = silu(x@wg^T)*(x@wu^T) ========
// CTA 128m x 128n, K-chunk 64. 512 threads = 16 warps (4m x 4n); warp 32m x 32n DUAL.
// 3-stage cp.async, ONE barrier per chunk. Rows padded to 72 halves (144 B).
#define ROWB 144
#define G1_AB (128 * ROWB)                    // 18432 B
#define G1_BB (128 * ROWB)                    // 18432 B
#define G1_BUFB (G1_AB + 2 * G1_BB)           // 55296 B
#define G1_SMEM (1024 + 3 * G1_BUFB)          // 166912 B
__global__ void __launch_bounds__(512, 1) k_gemm1() {
    int e   = blockIdx.z;
    int cnt = g_count[e];
    int m0  = blockIdx.x * 128;
    if (m0 >= cnt) return;
    int off = g_offset[e];
    int n0  = blockIdx.y * 128;

    extern __shared__ char smc[];
    int* toks = (int*)smc;
    char* bufs = smc + 1024;

    int tid = threadIdx.x;
    int lane = tid & 31, wid = tid >> 5;
    int warp_m = wid >> 2, warp_n = wid & 3;   // 4 x 4
    int g = lane >> 2, tig = lane & 3;

    if (tid < 128) {
        int m = m0 + tid; if (m >= cnt) m = cnt - 1;
        toks[tid] = g_row_tok[off + tid < off + cnt ? off + tid : off + cnt - 1];
    }
    // (re-do cleanly to avoid any subtlety)
    if (tid < 128) {
        int m = m0 + tid; if (m >= cnt) m = cnt - 1;
        toks[tid] = g_row_tok[off + m];
    }
    __syncthreads();

    const __half* wgE = g_wgh + (size_t)e * Id * Hd;
    const __half* wuE = g_wuh + (size_t)e * Id * Hd;
    uint32_t smb = smem_u32(bufs);

    // per-lane ldmatrix base offsets (within buffer)
    uint32_t a_lo[2], b_lo[4];
#pragma unroll
    for (int i = 0; i < 2; i++) {
        int r = warp_m * 32 + i * 16 + (lane & 15);
        a_lo[i] = r * ROWB + (lane >> 4) * 16;
    }
#pragma unroll
    for (int j = 0; j < 4; j++) {
        int n = warp_n * 32 + j * 8 + (lane & 7);
        b_lo[j] = n * ROWB + ((lane >> 3) & 1) * 16;
    }

    auto prefetch = [&](int c) {
        int k0 = c * 64;
        uint32_t dstb = smb + (c % 3) * G1_BUFB;
#pragma unroll
        for (int p = 0; p < 2; p++) {           // A: 128 rows x 8 quads = 1024 slots
            int idx = tid + 512 * p;
            int r = idx >> 3, q = idx & 7;
            CP16(dstb + r * ROWB + q * 16, g_xh + (size_t)toks[r] * Hd + k0 + q * 8);
        }
#pragma unroll
        for (int p = 0; p < 2; p++) {           // Bg/Bu: 128 x 8 = 1024 slots each
            int idx = tid + 512 * p;
            int r = idx >> 3, q = idx & 7;
            CP16(dstb + G1_AB + r * ROWB + q * 16,
                 wgE + (size_t)(n0 + r) * Hd + k0 + q * 8);
            CP16(dstb + G1_AB + G1_BB + r * ROWB + q * 16,
                 wuE + (size_t)(n0 + r) * Hd + k0 + q * 8);
        }
    };

    float cg[2][4][4] = {}, cu[2][4][4] = {};

    prefetch(0); cp_commit();
    prefetch(1); cp_commit();

    const int NCH = Hd / 64;  // 16
    for (int ch = 0; ch < NCH; ch++) {
        if (ch < NCH - 1) cp_wait1(); else cp_wait0();
        __syncthreads();
        if (ch + 2 < NCH) { prefetch(ch + 2); cp_commit(); }

        uint32_t bb = smb + (ch % 3) * G1_BUFB;
#pragma unroll
        for (int kk = 0; kk < 4; kk++) {
            uint32_t ko = kk * 32;             // 16 halves = 32 B per kk
            uint32_t a[2][4];
#pragma unroll
            for (int i = 0; i < 2; i++)
                LDSM4(a[i][0], a[i][1], a[i][2], a[i][3], bb + a_lo[i] + ko);
#pragma unroll
            for (int j = 0; j < 4; j++) {
                uint32_t bg0, bg1, bu0, bu1;
                LDSM2(bg0, bg1, bb + G1_AB + b_lo[j] + ko);
                LDSM2(bu0, bu1, bb + G1_AB + G1_BB + b_lo[j] + ko);
#pragma unroll
                for (int i = 0; i < 2; i++) {
                    MMA_F16(cg[i][j], a[i], bg0, bg1);
                    MMA_F16(cu[i][j], a[i], bu0, bu1);
                }
            }
        }
    }

    // epilogue: silu(gate)*up -> g_hidden_h
#pragma unroll
    for (int i = 0; i < 2; i++) {
        int rb = m0 + warp_m * 32 + i * 16 + g;
#pragma unroll
        for (int j = 0; j < 4; j++) {
            int n = n0 + warp_n * 32 + j * 8 + 2 * tig;
            if (rb < cnt) {
                size_t base = (size_t)(off + rb) * Id + n;
                float g0 = cg[i][j][0], g1 = cg[i][j][1];
                float h0 = g0 / (1.f + expf(-g0)) * cu[i][j][0];
                float h1 = g1 / (1.f + expf(-g1)) * cu[i][j][1];
                *(__half2*)(g_hidden_h + base) = __floats2half2_rn(h0, h1);
            }
            if (rb + 8 < cnt) {
                size_t base = (size_t)(off + rb + 8) * Id + n;
                float g2 = cg[i][j][2], g3 = cg[i][j][3];
                float h2 = g2 / (1.f + expf(-g2)) * cu[i][j][2];
                float h3 = g3 / (1.f + expf(-g3)) * cu[i][j][3];
                *(__half2*)(g_hidden_h + base) = __floats2half2_rn(h2, h3);
            }
        }
    }
}

// ================= GEMM2 (fp16 MMA + ldmatrix): down = hidden @ wd^T =================
// CTA 256m x 128n, K-chunk 64. 512 threads = 16 warps (4m x 4n); warp 64m x 32n.
// 3-stage cp.async, ONE barrier per chunk.
#define G2_AB (256 * ROWB)                    // 36864 B
#define G2_BB (128 * ROWB)                    // 18432 B
#define G2_BUFB (G2_AB + G2_BB)               // 55296 B
#define G2_SMEM (3 * G2_BUFB)                 // 165888 B
__global__ void __launch_bounds__(512, 1) k_gemm2() {
    int e   = blockIdx.z;
    int cnt = g_count[e];
    int m0  = blockIdx.x * 256;
    if (m0 >= cnt) return;
    int off = g_offset[e];
    int n0  = blockIdx.y * 128;

    extern __shared__ char smc[];
    char* bufs = smc;

    int tid = threadIdx.x;
    int lane = tid & 31, wid = tid >> 5;
    int warp_m = wid >> 2, warp_n = wid & 3;   // 4 x 4
    int g = lane >> 2, tig = lane & 3;

    const __half* wdE = g_wdh + (size_t)e * Hd * Id;
    uint32_t smb = smem_u32(bufs);

    uint32_t a_lo[4], b_lo[4];
#pragma unroll
    for (int i = 0; i < 4; i++) {
        int r = warp_m * 64 + i * 16 + (lane & 15);
        a_lo[i] = r * ROWB + (lane >> 4) * 16;
    }
#pragma unroll
    for (int j = 0; j < 4; j++) {
        int n = warp_n * 32 + j * 8 + (lane & 7);
        b_lo[j] = n * ROWB + ((lane >> 3) & 1) * 16;
    }

    auto prefetch = [&](int c) {
        int k0 = c * 64;
        uint32_t dstb = smb + (c % 3) * G2_BUFB;
#pragma unroll
        for (int p = 0; p < 4; p++) {           // A: 256 x 8 = 2048 slots
            int idx = tid + 512 * p;
            int r = idx >> 3, q = idx & 7;
            int am = m0 + r; if (am >= cnt) am = cnt - 1;
            CP16(dstb + r * ROWB + q * 16,
                 g_hidden_h + (size_t)(off + am) * Id + k0 + q * 8);
        }
#pragma unroll
        for (int p = 0; p < 2; p++) {           // B: 128 x 8 = 1024 slots
            int idx = tid + 512 * p;
            int r = idx >> 3, q = idx & 7;
            CP16(dstb + G2_AB + r * ROWB + q * 16,
                 wdE + (size_t)(n0 + r) * Id + k0 + q * 8);
        }
    };

    float c[4][4][4] = {};

    prefetch(0); cp_commit();
    prefetch(1); cp_commit();

    const int NCH = Id / 64;  // 64
    for (int ch = 0; ch < NCH; ch++) {
        if (ch < NCH - 1) cp_wait1(); else cp_wait0();
        __syncthreads();
        if (ch + 2 < NCH) { prefetch(ch + 2); cp_commit(); }

        uint32_t bb = smb + (ch % 3) * G2_BUFB;
#pragma unroll
        for (int kk = 0; kk < 4; kk++) {
            uint32_t ko = kk * 32;
            uint32_t a[4][4];
#pragma unroll
            for (int i = 0; i < 4; i++)
                LDSM4(a[i][0], a[i][1], a[i][2], a[i][3], bb + a_lo[i] + ko);
#pragma unroll
            for (int j = 0; j < 4; j++) {
                uint32_t b0, b1;
                LDSM2(b0, b1, bb + G2_AB + b_lo[j] + ko);
#pragma unroll
                for (int i = 0; i < 4; i++) MMA_F16(c[i][j], a[i], b0, b1);
            }
        }
    }

#pragma unroll
    for (int i = 0; i < 4; i++) {
        int rb = m0 + warp_m * 64 + i * 16 + g;
#pragma unroll
        for (int j = 0; j < 4; j++) {
            int n = n0 + warp_n * 32 + j * 8 + 2 * tig;
            if (rb < cnt) {
                size_t base = (size_t)(off + rb) * Hd + n;
                g_down[base]     = c[i][j][0];
                g_down[base + 1] = c[i][j][1];
            }
            if (rb + 8 < cnt) {
                size_t base = (size_t)(off + rb + 8) * Hd + n;
                g_down[base]     = c[i][j][2];
                g_down[base + 1] = c[i][j][3];
            }
        }
    }
}

// ---------------- combine ----------------
__global__ void __launch_bounds__(256) k_combine(float* __restrict__ out) {
    int idx = blockIdx.x * 256 + threadIdx.x;
    int t   = idx >> 8;
    int c4  = (idx & 255) << 2;
    int r0  = g_tok_row[t * 2];
    int r1  = g_tok_row[t * 2 + 1];
    float w0 = g_top_w[t * 2];
    float w1 = g_top_w[t * 2 + 1];
    float4 d0 = *(const float4*)(g_down + (size_t)r0 * Hd + c4);
    float4 d1 = *(const float4*)(g_down + (size_t)r1 * Hd + c4);
    float4 o;
    o.x = w0 * d0.x + w1 * d1.x;
    o.y = w0 * d0.y + w1 * d1.y;
    o.z = w0 * d0.z + w1 * d1.z;
    o.w = w0 * d0.w + w1 * d1.w;
    *(float4*)(out + (size_t)t * Hd + c4) = o;
}

// ---------------- launch ----------------
extern "C" void kernel_launch(void* const* d_in, const int* in_sizes, int n_in,
                              void* d_out, int out_size) {
    const float* x  = (const float*)d_in[0];
    const float* gw = (const float*)d_in[1];
    const float* wg = (const float*)d_in[2];
    const float* wu = (const float*)d_in[3];
    const float* wd = (const float*)d_in[4];
    float* out = (float*)d_out;

    cudaFuncSetAttribute(k_gemm1, cudaFuncAttributeMaxDynamicSharedMemorySize, G1_SMEM);
    cudaFuncSetAttribute(k_gemm2, cudaFuncAttributeMaxDynamicSharedMemorySize, G2_SMEM);

    // launch 0: converts + init
    k_prep<<<XB + 3 * WB, 256>>>(x, wg, wu, wd);
    // launch 1: router
    k_router<<<Tn / 8, 256>>>(x, gw);
    // launch 2: assign
    k_assign<<<Tn / 256, 256>>>();

    // launch 3: GEMM1 (ncu profiles launch index 3)
    dim3 g1(32, 32, Ed);   // (4096/128) x (4096/128) x experts
    k_gemm1<<<g1, 512, G1_SMEM>>>();

    // launch 4: GEMM2
    dim3 g2(16, 8, Ed);    // (4096/256) x (1024/128) x experts
    k_gemm2<<<g2, 512, G2_SMEM>>>();

    // launch 5: combine
    k_combine<<<Tn * Hd / 1024, 256>>>(out);
}